// round 6
// baseline (speedup 1.0000x reference)
#include <cuda_runtime.h>
#include <cstdint>
#include <cstddef>

#define F 128
#define MAXN 100000
#define MAXE 1600000

// Scratch (allocation-free rule: __device__ globals). 16B-aligned for float4.
__device__ __align__(16) float g_h[MAXN * F];     // post-GEMM features
__device__ __align__(16) float g_agg[MAXN * F];   // aggregation accumulator
__device__ __align__(16) float g_y[MAXN * F];     // layer-1 activated output
__device__ float g_dinv[MAXN];                    // deg^{-1/2}
__device__ float g_Wt[F * F];                     // W transposed
__device__ int   g_src[MAXE];
__device__ int   g_dst[MAXE];
__device__ int   g_is64;

// ---------------- edge_index dtype detection + decode ----------------
// int64 values < 100000 -> every high 32-bit word is 0. For int32 random
// indices, 256 consecutive zeros is impossible. One thread decides.
__global__ void k_detect(const int* __restrict__ w, int E) {
    if (blockIdx.x == 0 && threadIdx.x == 0) {
        int all0 = 1;
        int cnt = E < 256 ? E : 256;
        for (int i = 0; i < cnt; i++)
            if (w[2 * i + 1] != 0) { all0 = 0; break; }
        g_is64 = all0;
    }
}

__global__ void k_decode(const int* __restrict__ w, int E) {
    int e = blockIdx.x * blockDim.x + threadIdx.x;
    if (e < E) {
        if (g_is64) {
            g_src[e] = w[2 * e];            // little-endian low word
            g_dst[e] = w[2 * (E + e)];
        } else {
            g_src[e] = w[e];
            g_dst[e] = w[E + e];
        }
    }
}

// ---------------- degree ----------------
__global__ void k_init_deg(int n) {
    int i = blockIdx.x * blockDim.x + threadIdx.x;
    if (i < n) g_dinv[i] = 1.0f;   // self-loop contributes 1
}

__global__ void k_count_deg(int E, int n) {
    int e = blockIdx.x * blockDim.x + threadIdx.x;
    if (e < E) {
        int d = g_dst[e];
        if ((unsigned)d < (unsigned)n) atomicAdd(&g_dinv[d], 1.0f);  // -> RED
    }
}

__global__ void k_rsqrt(int n) {
    int i = blockIdx.x * blockDim.x + threadIdx.x;
    if (i < n) g_dinv[i] = rsqrtf(g_dinv[i]);
}

// ---------------- W transpose ----------------
__global__ void k_transpose(const float* __restrict__ W) {
    int i = blockIdx.x * blockDim.x + threadIdx.x;  // 16384 threads
    int j = i >> 7, k = i & 127;
    g_Wt[k * F + j] = W[i];
}

// ---------------- GEMM: h = in @ W^T ; agg = h*dinv^2 + b ----------------
// Block: 128 threads (thread = output column j), 32 node rows per block.
__global__ void __launch_bounds__(128) k_gemm(const float* __restrict__ in,
                                              const float* __restrict__ b,
                                              float* __restrict__ h,
                                              float* __restrict__ agg,
                                              int n) {
    __shared__ float xs[F * 36];   // xs[k*36 + r], pad avoids bank conflicts
    const int tid = threadIdx.x;
    const int node0 = blockIdx.x * 32;

#pragma unroll
    for (int r = 0; r < 32; r++) {
        int nn = node0 + r;
        xs[tid * 36 + r] = (nn < n) ? in[(size_t)nn * F + tid] : 0.0f;
    }
    __syncthreads();

    float acc[32];
#pragma unroll
    for (int r = 0; r < 32; r++) acc[r] = 0.0f;

    const int j = tid;
#pragma unroll 4
    for (int k = 0; k < F; k++) {
        float w = g_Wt[k * F + j];          // coalesced, L1-resident (64 KB)
        const float* xr = &xs[k * 36];      // broadcast reads
#pragma unroll
        for (int r = 0; r < 32; r++) acc[r] = fmaf(xr[r], w, acc[r]);
    }

    float bj = b[j];
#pragma unroll
    for (int r = 0; r < 32; r++) {
        int nn = node0 + r;
        if (nn < n) {
            float hv = acc[r];
            h[(size_t)nn * F + j] = hv;
            float di = g_dinv[nn];
            agg[(size_t)nn * F + j] = fmaf(hv, di * di, bj);
        }
    }
}

// ---------------- edge scatter: agg[dst] += h[src] * norm ----------------
// One warp per edge; each lane handles 4 floats (float4 load + 4 scalar REDs).
__global__ void __launch_bounds__(256) k_scatter(const float* __restrict__ h,
                                                 float* __restrict__ agg,
                                                 int E, int n) {
    const int lane = threadIdx.x & 31;
    const int warp = (blockIdx.x * blockDim.x + threadIdx.x) >> 5;
    const int nwarps = (gridDim.x * blockDim.x) >> 5;

    for (int e = warp; e < E; e += nwarps) {
        int s = g_src[e];
        int d = g_dst[e];
        if ((unsigned)s >= (unsigned)n || (unsigned)d >= (unsigned)n) continue;
        float norm = g_dinv[s] * g_dinv[d];
        const float4* hp = (const float4*)(h + (size_t)s * F);
        float4 v = hp[lane];
        float* ap = agg + (size_t)d * F + lane * 4;
        atomicAdd(ap + 0, v.x * norm);   // result unused -> RED.E.ADD.F32
        atomicAdd(ap + 1, v.y * norm);
        atomicAdd(ap + 2, v.z * norm);
        atomicAdd(ap + 3, v.w * norm);
    }
}

// ---------------- leaky relu (vectorized) ----------------
__global__ void k_lrelu4(const float* __restrict__ a, float* __restrict__ o, int cnt4) {
    int i = blockIdx.x * blockDim.x + threadIdx.x;
    if (i < cnt4) {
        float4 v = ((const float4*)a)[i];
        v.x = v.x > 0.0f ? v.x : 0.01f * v.x;
        v.y = v.y > 0.0f ? v.y : 0.01f * v.y;
        v.z = v.z > 0.0f ? v.z : 0.01f * v.z;
        v.w = v.w > 0.0f ? v.w : 0.01f * v.w;
        ((float4*)o)[i] = v;
    }
}

extern "C" void kernel_launch(void* const* d_in, const int* in_sizes, int n_in,
                              void* d_out, int out_size) {
    // Assign inputs by element count (robust to ordering):
    //   x: N*128 (largest), edge_index: 2E, W: 128*128=16384 (x2), b: 128 (x2)
    const float* x = nullptr; const int* ei = nullptr;
    const float* W1 = nullptr; const float* b1 = nullptr;
    const float* W2 = nullptr; const float* b2 = nullptr;
    int x_elems = 0, ei_elems = 0;

    for (int i = 0; i < n_in; i++) {
        int s = in_sizes[i];
        if (s == F * F)      { if (!W1) W1 = (const float*)d_in[i]; else W2 = (const float*)d_in[i]; }
        else if (s == F)     { if (!b1) b1 = (const float*)d_in[i]; else b2 = (const float*)d_in[i]; }
        else if (s > 4 * F * F) {
            // two big buffers: x (N*128) and edge_index (2E); x is bigger here
            if (!x) { x = (const float*)d_in[i]; x_elems = s; }
            else    { ei = (const int*)d_in[i]; ei_elems = s; }
        }
    }
    if (x && ei && x_elems < ei_elems) {  // swap if edge buffer came first & larger
        const float* t = x; x = (const float*)ei; ei = (const int*)t;
        int te = x_elems; x_elems = ei_elems; ei_elems = te;
    }

    const int N = x_elems / F;
    const int E = ei_elems / 2;
    float* out = (float*)d_out;

    float *h, *agg, *y;
    cudaGetSymbolAddress((void**)&h,   g_h);
    cudaGetSymbolAddress((void**)&agg, g_agg);
    cudaGetSymbolAddress((void**)&y,   g_y);

    const int TB = 256;
    const int nblk  = (N + TB - 1) / TB;
    const int eblk  = (E + TB - 1) / TB;
    const int gblk  = (N + 31) / 32;
    const int sblk  = 148 * 16;               // grid-stride scatter
    const int lblk  = (N * F / 4 + TB - 1) / TB;

    // decode edges (dtype-agnostic) + normalization
    k_detect<<<1, 32>>>(ei, E);
    k_decode<<<eblk, TB>>>(ei, E);
    k_init_deg<<<nblk, TB>>>(N);
    k_count_deg<<<eblk, TB>>>(E, N);
    k_rsqrt<<<nblk, TB>>>(N);

    // ---- layer 1 ----
    k_transpose<<<64, 256>>>(W1);
    k_gemm<<<gblk, 128>>>(x, b1, h, agg, N);
    k_scatter<<<sblk, TB>>>(h, agg, E, N);
    k_lrelu4<<<lblk, TB>>>(agg, y, N * F / 4);

    // ---- layer 2 ----
    k_transpose<<<64, 256>>>(W2);
    k_gemm<<<gblk, 128>>>(y, b2, h, agg, N);
    k_scatter<<<sblk, TB>>>(h, agg, E, N);
    k_lrelu4<<<lblk, TB>>>(agg, out, N * F / 4);
}

// round 7
// speedup vs baseline: 2.6730x; 2.6730x over previous
#include <cuda_runtime.h>
#include <cstdint>
#include <cstddef>

#define F 128
#define MAXN 100000
#define MAXE 1600000

// Scratch (allocation-free rule: __device__ globals). 16B-aligned for float4.
__device__ __align__(16) float g_h[MAXN * F];     // post-GEMM features
__device__ __align__(16) float g_y[MAXN * F];     // layer-1 activated output
__device__ float g_dinv[MAXN];                    // deg^{-1/2}
__device__ float g_Wt[F * F];                     // W transposed
__device__ int   g_src[MAXE];
__device__ int   g_dst[MAXE];
__device__ int   g_degi[MAXN];                    // in-degree histogram
__device__ int   g_off[MAXN + 1];                 // CSR row offsets (by dst)
__device__ int   g_cursor[MAXN];                  // placement cursors
__device__ int   g_csr_src[MAXE];                 // src ids grouped by dst
__device__ int   g_is64;

// ---------------- edge_index dtype detection + decode ----------------
__global__ void k_detect(const int* __restrict__ w, int E) {
    if (blockIdx.x == 0 && threadIdx.x == 0) {
        int all0 = 1;
        int cnt = E < 256 ? E : 256;
        for (int i = 0; i < cnt; i++)
            if (w[2 * i + 1] != 0) { all0 = 0; break; }
        g_is64 = all0;
    }
}

__global__ void k_decode(const int* __restrict__ w, int E) {
    int e = blockIdx.x * blockDim.x + threadIdx.x;
    if (e < E) {
        if (g_is64) {
            g_src[e] = w[2 * e];
            g_dst[e] = w[2 * (E + e)];
        } else {
            g_src[e] = w[e];
            g_dst[e] = w[E + e];
        }
    }
}

// ---------------- degree histogram (re-zeroed every replay) ----------------
__global__ void k_zero_deg(int n) {
    int i = blockIdx.x * blockDim.x + threadIdx.x;
    if (i < n) g_degi[i] = 0;
}

__global__ void k_count_deg(int E, int n) {
    int e = blockIdx.x * blockDim.x + threadIdx.x;
    if (e < E) {
        int d = g_dst[e];
        if ((unsigned)d < (unsigned)n) atomicAdd(&g_degi[d], 1);
    }
}

__global__ void k_rsqrt(int n) {
    int i = blockIdx.x * blockDim.x + threadIdx.x;
    if (i < n) g_dinv[i] = rsqrtf((float)g_degi[i] + 1.0f);
}

// ---------------- exclusive scan over degrees -> CSR offsets ----------------
// Single block, 1024 threads, sequential 1024-chunks with in-block scan.
__global__ void __launch_bounds__(1024) k_scan(int n) {
    __shared__ int warp_base[32];
    __shared__ int carry;
    const int tid = threadIdx.x;
    const int lane = tid & 31, wid = tid >> 5;
    if (tid == 0) carry = 0;
    __syncthreads();

    for (int start = 0; start < n; start += 1024) {
        int i = start + tid;
        int v = (i < n) ? g_degi[i] : 0;
        // inclusive scan within warp
        int x = v;
#pragma unroll
        for (int o = 1; o < 32; o <<= 1) {
            int y = __shfl_up_sync(0xffffffffu, x, o);
            if (lane >= o) x += y;
        }
        if (lane == 31) warp_base[wid] = x;
        __syncthreads();
        if (tid < 32) {
            int w = warp_base[tid];
            int y = w;
#pragma unroll
            for (int o = 1; o < 32; o <<= 1) {
                int z = __shfl_up_sync(0xffffffffu, y, o);
                if (tid >= o) y += z;
            }
            warp_base[tid] = y - w;   // exclusive base per warp
        }
        __syncthreads();
        int excl = carry + warp_base[wid] + (x - v);
        if (i < n) { g_off[i] = excl; g_cursor[i] = excl; }
        __syncthreads();
        if (tid == 1023) carry += warp_base[31] + x;   // add chunk total
        __syncthreads();
    }
    if (tid == 0) g_off[n] = carry;
}

// ---------------- edge placement: group src by dst ----------------
__global__ void k_place(int E, int n) {
    int e = blockIdx.x * blockDim.x + threadIdx.x;
    if (e < E) {
        int d = g_dst[e];
        int s = g_src[e];
        if ((unsigned)d < (unsigned)n && (unsigned)s < (unsigned)n) {
            int pos = atomicAdd(&g_cursor[d], 1);
            g_csr_src[pos] = s;
        }
    }
}

// ---------------- W transpose ----------------
__global__ void k_transpose(const float* __restrict__ W) {
    int i = blockIdx.x * blockDim.x + threadIdx.x;  // 16384 threads
    int j = i >> 7, k = i & 127;
    g_Wt[k * F + j] = W[i];
}

// ---------------- GEMM: h = in @ W^T ----------------
__global__ void __launch_bounds__(128) k_gemm(const float* __restrict__ in,
                                              float* __restrict__ h,
                                              int n) {
    __shared__ float xs[F * 36];
    const int tid = threadIdx.x;
    const int node0 = blockIdx.x * 32;

#pragma unroll
    for (int r = 0; r < 32; r++) {
        int nn = node0 + r;
        xs[tid * 36 + r] = (nn < n) ? in[(size_t)nn * F + tid] : 0.0f;
    }
    __syncthreads();

    float acc[32];
#pragma unroll
    for (int r = 0; r < 32; r++) acc[r] = 0.0f;

    const int j = tid;
#pragma unroll 4
    for (int k = 0; k < F; k++) {
        float w = g_Wt[k * F + j];
        const float* xr = &xs[k * 36];
#pragma unroll
        for (int r = 0; r < 32; r++) acc[r] = fmaf(xr[r], w, acc[r]);
    }

#pragma unroll
    for (int r = 0; r < 32; r++) {
        int nn = node0 + r;
        if (nn < n) h[(size_t)nn * F + j] = acc[r];
    }
}

// ---------------- fused aggregation + self-loop + bias + leaky-relu ---------
// One warp per dst node; lane handles 4 features (float4). No atomics.
__global__ void __launch_bounds__(256) k_agg(const float* __restrict__ h,
                                             const float* __restrict__ b,
                                             float* __restrict__ o,
                                             int n) {
    const int lane = threadIdx.x & 31;
    const int d = (blockIdx.x * blockDim.x + threadIdx.x) >> 5;
    if (d >= n) return;

    const int beg = g_off[d];
    const int end = g_off[d + 1];
    const float did = g_dinv[d];

    float4 hv = ((const float4*)(h + (size_t)d * F))[lane];
    float4 bb = ((const float4*)b)[lane];
    const float sw = did * did;
    float4 acc;
    acc.x = fmaf(hv.x, sw, bb.x);
    acc.y = fmaf(hv.y, sw, bb.y);
    acc.z = fmaf(hv.z, sw, bb.z);
    acc.w = fmaf(hv.w, sw, bb.w);

    int j = beg;
    for (; j + 1 < end; j += 2) {            // 2-wide for MLP
        int s0 = g_csr_src[j];
        int s1 = g_csr_src[j + 1];
        float n0 = g_dinv[s0] * did;
        float n1 = g_dinv[s1] * did;
        float4 v0 = ((const float4*)(h + (size_t)s0 * F))[lane];
        float4 v1 = ((const float4*)(h + (size_t)s1 * F))[lane];
        acc.x = fmaf(v0.x, n0, acc.x); acc.y = fmaf(v0.y, n0, acc.y);
        acc.z = fmaf(v0.z, n0, acc.z); acc.w = fmaf(v0.w, n0, acc.w);
        acc.x = fmaf(v1.x, n1, acc.x); acc.y = fmaf(v1.y, n1, acc.y);
        acc.z = fmaf(v1.z, n1, acc.z); acc.w = fmaf(v1.w, n1, acc.w);
    }
    if (j < end) {
        int s0 = g_csr_src[j];
        float n0 = g_dinv[s0] * did;
        float4 v0 = ((const float4*)(h + (size_t)s0 * F))[lane];
        acc.x = fmaf(v0.x, n0, acc.x); acc.y = fmaf(v0.y, n0, acc.y);
        acc.z = fmaf(v0.z, n0, acc.z); acc.w = fmaf(v0.w, n0, acc.w);
    }

    acc.x = acc.x > 0.0f ? acc.x : 0.01f * acc.x;
    acc.y = acc.y > 0.0f ? acc.y : 0.01f * acc.y;
    acc.z = acc.z > 0.0f ? acc.z : 0.01f * acc.z;
    acc.w = acc.w > 0.0f ? acc.w : 0.01f * acc.w;
    ((float4*)(o + (size_t)d * F))[lane] = acc;
}

extern "C" void kernel_launch(void* const* d_in, const int* in_sizes, int n_in,
                              void* d_out, int out_size) {
    // Assign inputs by element count (robust to ordering).
    const float* x = nullptr; const int* ei = nullptr;
    const float* W1 = nullptr; const float* b1 = nullptr;
    const float* W2 = nullptr; const float* b2 = nullptr;
    int x_elems = 0, ei_elems = 0;

    for (int i = 0; i < n_in; i++) {
        int s = in_sizes[i];
        if (s == F * F)      { if (!W1) W1 = (const float*)d_in[i]; else W2 = (const float*)d_in[i]; }
        else if (s == F)     { if (!b1) b1 = (const float*)d_in[i]; else b2 = (const float*)d_in[i]; }
        else if (s > 4 * F * F) {
            if (!x) { x = (const float*)d_in[i]; x_elems = s; }
            else    { ei = (const int*)d_in[i]; ei_elems = s; }
        }
    }
    if (x && ei && x_elems < ei_elems) {
        const float* t = x; x = (const float*)ei; ei = (const int*)t;
        int te = x_elems; x_elems = ei_elems; ei_elems = te;
    }

    const int N = x_elems / F;
    const int E = ei_elems / 2;
    float* out = (float*)d_out;

    float *h, *y;
    cudaGetSymbolAddress((void**)&h, g_h);
    cudaGetSymbolAddress((void**)&y, g_y);

    const int TB = 256;
    const int nblk = (N + TB - 1) / TB;
    const int eblk = (E + TB - 1) / TB;
    const int gblk = (N + 31) / 32;
    const int ablk = (N * 32 + TB - 1) / TB;   // warp per node

    // edges -> canonical int32, degrees, CSR
    k_detect<<<1, 32>>>(ei, E);
    k_decode<<<eblk, TB>>>(ei, E);
    k_zero_deg<<<nblk, TB>>>(N);
    k_count_deg<<<eblk, TB>>>(E, N);
    k_rsqrt<<<nblk, TB>>>(N);
    k_scan<<<1, 1024>>>(N);
    k_place<<<eblk, TB>>>(E, N);

    // ---- layer 1 ----
    k_transpose<<<64, 256>>>(W1);
    k_gemm<<<gblk, 128>>>(x, h, N);
    k_agg<<<ablk, TB>>>(h, b1, y, N);

    // ---- layer 2 ----
    k_transpose<<<64, 256>>>(W2);
    k_gemm<<<gblk, 128>>>(y, h, N);
    k_agg<<<ablk, TB>>>(h, b2, out, N);
}